// round 11
// baseline (speedup 1.0000x reference)
#include <cuda_runtime.h>
#include <cuda_pipeline.h>
#include <math_constants.h>

#define NA    2     // anchors per block
#define GRID  128   // 128 * 2 = 256 anchors, single wave on 148 SMs
#define NT    256   // 8 warps; warp w owns rows [32w, 32w+32)
#define ROWW  132   // padded row stride (floats): conflict-free LDS.128

__device__ float        g_sum;
__device__ float        g_cnt;
__device__ unsigned int g_ticket;

extern __shared__ float semb[];   // 256 * ROWW floats = 135168 B (dynamic)

__global__ void __launch_bounds__(NT, 1)
triplet_fused(const float* __restrict__ emb,
              const int* __restrict__ labraw,
              float* __restrict__ out) {
    __shared__ float sanch[8][NA * 128 + 4];   // per-warp anchor copies
    __shared__ float dnegS[NA][260];           // d[ia,j] if j negative else -inf
    __shared__ int   s_npos;
    __shared__ float s_bsum;

    const int t    = threadIdx.x;
    const int lane = t & 31;
    const int w    = t >> 5;
    const int ib   = blockIdx.x * NA;

    if (t == 0) { s_npos = 0; s_bsum = 0.f; }  // smem atomics happen post-barrier

    // warp-local dtype detect: hi words of elements 0..31 (first 256B; in-bounds
    // for both int32[256] and int64[256]; P(int32 aliasing) ~ 16^-32)
    const int hidet = labraw[2 * lane + 1];

    // ---- warp-private async staging: warp w stages rows [32w,32w+32) + anchors ----
    const float4* src = (const float4*)emb;            // 32 float4 per row
    float*        anc = sanch[w];
    #pragma unroll
    for (int a = 0; a < NA; a++)
        __pipeline_memcpy_async(anc + a * 128 + lane * 4, src + (ib + a) * 32 + lane, 16);
    #pragma unroll
    for (int k = 0; k < 32; k++) {
        const int r = 32 * w + k;
        __pipeline_memcpy_async(semb + r * ROWW + lane * 4, src + r * 32 + lane, 16);
    }
    __pipeline_commit();

    const bool is64 = !__any_sync(~0u, hidet != 0);

    // label loads (L2-hot) overlapped with the staging wait
    const int labT  = is64 ? labraw[2 * t]        : labraw[t];
    const int labA0 = is64 ? labraw[2 * ib]       : labraw[ib];
    const int labA1 = is64 ? labraw[2 * (ib + 1)] : labraw[ib + 1];

    __pipeline_wait_prior(0);
    __syncwarp();          // this warp reads only rows/anchors staged by this warp

    // ---- anchor norms per warp: lane partial + shfl tree (common-mode in dk) ----
    float an0, an1;
    {
        float4 qa = *(const float4*)(anc + lane * 4);
        float4 qb = *(const float4*)(anc + 128 + lane * 4);
        an0 = qa.x * qa.x + qa.y * qa.y + qa.z * qa.z + qa.w * qa.w;
        an1 = qb.x * qb.x + qb.y * qb.y + qb.z * qb.z + qb.w * qb.w;
        #pragma unroll
        for (int off = 16; off; off >>= 1) {
            an0 += __shfl_xor_sync(~0u, an0, off);
            an1 += __shfl_xor_sync(~0u, an1, off);
        }
    }

    // ---- phase 1: dot of row t vs NA anchors (R7 ordering) ----
    const float* rowT = semb + t * ROWW;
    float d0 = 0.f, d1 = 0.f, nj = 0.f;
    #pragma unroll
    for (int c = 0; c < 128; c += 4) {
        float4 a  = *(const float4*)(rowT + c);
        float4 b0 = *(const float4*)(anc + c);         // broadcast LDS
        float4 b1 = *(const float4*)(anc + 128 + c);
        nj += a.x * a.x  + a.y * a.y  + a.z * a.z  + a.w * a.w;
        d0 += a.x * b0.x + a.y * b0.y + a.z * b0.z + a.w * b0.w;
        d1 += a.x * b1.x + a.y * b1.y + a.z * b1.z + a.w * b1.w;
    }

    // ---- dk, neg mask — no block barrier needed before the write ----
    const float dk0 = sqrtf(fmaxf(an0 + nj - 2.f * d0, 1e-4f));
    const float dk1 = sqrtf(fmaxf(an1 + nj - 2.f * d1, 1e-4f));
    const bool  pos0 = (labT == labA0) && (t != ib);       // (1-pos) incl. diagonal
    const bool  pos1 = (labT == labA1) && (t != ib + 1);
    dnegS[0][t] = pos0 ? -CUDART_INF_F : dk0;
    dnegS[1][t] = pos1 ? -CUDART_INF_F : dk1;

    const unsigned m0 = __ballot_sync(~0u, pos0);
    const unsigned m1 = __ballot_sync(~0u, pos1);
    const int c0    = __popc(m0);
    const int total = c0 + __popc(m1);

    __syncthreads();   // single main barrier: dnegS complete, s_npos/s_bsum inited

    if (lane == 0 && total) atomicAdd(&s_npos, total);

    // ---- phase 2: 4-lane-group cooperative scans, 8 positives per warp batch ----
    const int group = lane >> 2;
    const int sub   = lane & 3;
    float contrib = 0.f;
    for (int base = 0; base < total; base += 8) {
        const int  idx = base + group;
        const bool act = idx < total;
        const int  ii  = act ? idx : 0;
        const int  a   = (ii >= c0) ? 1 : 0;
        const unsigned srcl = (a ? __fns(m1, 0, ii - c0 + 1)
                                 : __fns(m0, 0, ii + 1)) & 31u;
        const float dva = __shfl_sync(~0u, dk0, srcl);
        const float dvb = __shfl_sync(~0u, dk1, srcl);
        const float dv  = a ? dvb : dva;

        const float4* dn = (const float4*)&dnegS[a][0];    // rows 1040B apart
        float n0 = CUDART_INF_F,  n1 = CUDART_INF_F,  n2 = CUDART_INF_F,  n3 = CUDART_INF_F;
        float x0 = -CUDART_INF_F, x1 = -CUDART_INF_F, x2 = -CUDART_INF_F, x3 = -CUDART_INF_F;
        #pragma unroll
        for (int j = 0; j < 16; j++) {                     // interleaved: chunk sub+4j
            float4 q = dn[sub + 4 * j];
            n0 = fminf(n0, q.x > dv ? q.x : CUDART_INF_F); x0 = fmaxf(x0, q.x);
            n1 = fminf(n1, q.y > dv ? q.y : CUDART_INF_F); x1 = fmaxf(x1, q.y);
            n2 = fminf(n2, q.z > dv ? q.z : CUDART_INF_F); x2 = fmaxf(x2, q.z);
            n3 = fminf(n3, q.w > dv ? q.w : CUDART_INF_F); x3 = fmaxf(x3, q.w);
        }
        float mn = fminf(fminf(n0, n1), fminf(n2, n3));
        float mx = fmaxf(fmaxf(x0, x1), fmaxf(x2, x3));
        // 2-level reduce within the 4-lane group
        mn = fminf(mn, __shfl_xor_sync(~0u, mn, 1)); mx = fmaxf(mx, __shfl_xor_sync(~0u, mx, 1));
        mn = fminf(mn, __shfl_xor_sync(~0u, mn, 2)); mx = fmaxf(mx, __shfl_xor_sync(~0u, mx, 2));
        if (act && sub == 0) {
            const float v = (mn < CUDART_INF_F) ? (dv - mn)   // semi-hard exists
                                                : (dv - mx);  // fallback: easiest neg
            contrib += fmaxf(v + 1.0f, 0.f);                  // relu(semi_hard + MARGIN)
        }
    }
    #pragma unroll
    for (int off = 16; off; off >>= 1) contrib += __shfl_xor_sync(~0u, contrib, off);
    if (lane == 0 && contrib != 0.f) atomicAdd(&s_bsum, contrib);
    __syncthreads();

    // ---- last-block-done epilogue (single kernel) ----
    if (t == 0) {
        atomicAdd(&g_sum, s_bsum);
        atomicAdd(&g_cnt, (float)s_npos);
        __threadfence();
        unsigned tk = atomicAdd(&g_ticket, 1u);
        if (tk == GRID - 1) {
            __threadfence();
            float s = atomicAdd(&g_sum, 0.f);
            float c = atomicAdd(&g_cnt, 0.f);
            out[0] = s / c;
            g_sum = 0.f;          // reset for next graph replay
            g_cnt = 0.f;
            __threadfence();
            g_ticket = 0u;
        }
    }
}

extern "C" void kernel_launch(void* const* d_in, const int* in_sizes, int n_in,
                              void* d_out, int out_size) {
    const float* emb    = (const float*)d_in[0];   // [256, 128] float32
    const int*   labraw = (const int*)d_in[1];     // [256] labels (int64/int32 detected)
    float* out = (float*)d_out;

    const int smem = 256 * ROWW * sizeof(float);   // 135168 B
    cudaFuncSetAttribute(triplet_fused, cudaFuncAttributeMaxDynamicSharedMemorySize, smem);
    triplet_fused<<<GRID, NT, smem>>>(emb, labraw, out);
}

// round 15
// speedup vs baseline: 1.3409x; 1.3409x over previous
#include <cuda_runtime.h>
#include <cuda_pipeline.h>
#include <math_constants.h>

#define NA    2     // anchors per block
#define GRID  128   // 128 * 2 = 256 anchors, single wave on 148 SMs
#define NT    256   // 8 warps; warp w owns rows [32w, 32w+32)
#define ROWW  132   // padded row stride (floats): conflict-free LDS.128

__device__ float        g_sum;
__device__ float        g_cnt;
__device__ unsigned int g_ticket;

extern __shared__ float semb[];   // 256 * ROWW floats = 135168 B (dynamic)

__global__ void __launch_bounds__(NT, 1)
triplet_fused(const float* __restrict__ emb,
              const int* __restrict__ labraw,
              float* __restrict__ out) {
    __shared__ float sanch[8][NA * 128 + 4];   // per-warp anchor copies
    __shared__ float dnegS[NA][260];           // d[ia,j] if j negative else -inf
    __shared__ float dkS[NA][260];             // d[ia,j]
    __shared__ int   s_plist[NA * 256];
    __shared__ int   s_npos;
    __shared__ float s_bsum;

    const int t    = threadIdx.x;
    const int lane = t & 31;
    const int w    = t >> 5;
    const int ib   = blockIdx.x * NA;

    if (t == 0) { s_npos = 0; s_bsum = 0.f; }  // consumed only after the barrier

    // warp-local dtype detect: hi words of elements 0..31 (first 256B; in-bounds
    // for both int32[256] and int64[256]; P(int32 aliasing all-zero) ~ 16^-32)
    const int hidet = labraw[2 * lane + 1];

    // ---- warp-private async staging: warp w stages rows [32w,32w+32) + anchors ----
    const float4* src = (const float4*)emb;            // 32 float4 per row
    float*        anc = sanch[w];
    #pragma unroll
    for (int a = 0; a < NA; a++)
        __pipeline_memcpy_async(anc + a * 128 + lane * 4, src + (ib + a) * 32 + lane, 16);
    #pragma unroll
    for (int k = 0; k < 32; k++) {
        const int r = 32 * w + k;
        __pipeline_memcpy_async(semb + r * ROWW + lane * 4, src + r * 32 + lane, 16);
    }
    __pipeline_commit();

    const bool is64 = !__any_sync(~0u, hidet != 0);

    // label loads (L2-hot) overlapped with the staging wait
    const int labT  = is64 ? labraw[2 * t]        : labraw[t];
    const int labA0 = is64 ? labraw[2 * ib]       : labraw[ib];
    const int labA1 = is64 ? labraw[2 * (ib + 1)] : labraw[ib + 1];

    __pipeline_wait_prior(0);
    __syncwarp();          // this warp reads only rows/anchors staged by this warp

    // ---- anchor norms per warp: lane partial + shfl tree (overlaps LDS warmup) ----
    float an0, an1;
    {
        float4 qa = *(const float4*)(anc + lane * 4);
        float4 qb = *(const float4*)(anc + 128 + lane * 4);
        an0 = qa.x * qa.x + qa.y * qa.y + qa.z * qa.z + qa.w * qa.w;
        an1 = qb.x * qb.x + qb.y * qb.y + qb.z * qb.z + qb.w * qb.w;
        #pragma unroll
        for (int off = 16; off; off >>= 1) {
            an0 += __shfl_xor_sync(~0u, an0, off);
            an1 += __shfl_xor_sync(~0u, an1, off);
        }
    }

    // ---- phase 1: dot of row t vs NA anchors (R7 ordering) ----
    const float* rowT = semb + t * ROWW;
    float d0 = 0.f, d1 = 0.f, nj = 0.f;
    #pragma unroll
    for (int c = 0; c < 128; c += 4) {
        float4 a  = *(const float4*)(rowT + c);
        float4 b0 = *(const float4*)(anc + c);         // broadcast LDS
        float4 b1 = *(const float4*)(anc + 128 + c);
        nj += a.x * a.x  + a.y * a.y  + a.z * a.z  + a.w * a.w;
        d0 += a.x * b0.x + a.y * b0.y + a.z * b0.z + a.w * b0.w;
        d1 += a.x * b1.x + a.y * b1.y + a.z * b1.z + a.w * b1.w;
    }

    // ---- dk, neg mask, positives list (no block barrier needed before writes) ----
    const float dk0  = sqrtf(fmaxf(an0 + nj - 2.f * d0, 1e-4f));
    const float dk1  = sqrtf(fmaxf(an1 + nj - 2.f * d1, 1e-4f));
    const bool  pos0 = (labT == labA0) && (t != ib);       // (1-pos) incl. diagonal
    const bool  pos1 = (labT == labA1) && (t != ib + 1);
    dkS[0][t] = dk0;                  dkS[1][t] = dk1;
    dnegS[0][t] = pos0 ? -CUDART_INF_F : dk0;
    dnegS[1][t] = pos1 ? -CUDART_INF_F : dk1;
    if (pos0) { int p = atomicAdd(&s_npos, 1); s_plist[p] = t; }          // a=0
    if (pos1) { int p = atomicAdd(&s_npos, 1); s_plist[p] = 256 + t; }    // a=1

    __syncthreads();   // barrier #1: dnegS/dkS/plist complete

    // ---- phase 2: thread-per-positive scan, min & max fused (R10-proven) ----
    const int np = s_npos;
    float contrib = 0.f;
    for (int p = t; p < np; p += NT) {
        const int   e   = s_plist[p];
        const int   a   = e >> 8;
        const int   k   = e & 255;
        const float dv  = dkS[a][k];
        const float4* dn = (const float4*)&dnegS[a][0];    // rows 1040B apart
        float m0 = CUDART_INF_F,  m1 = CUDART_INF_F,  m2 = CUDART_INF_F,  m3 = CUDART_INF_F;
        float x0 = -CUDART_INF_F, x1 = -CUDART_INF_F, x2 = -CUDART_INF_F, x3 = -CUDART_INF_F;
        #pragma unroll 8
        for (int j = 0; j < 64; j++) {                     // 64 x float4 = 256
            float4 q = dn[j];
            m0 = fminf(m0, q.x > dv ? q.x : CUDART_INF_F); x0 = fmaxf(x0, q.x);
            m1 = fminf(m1, q.y > dv ? q.y : CUDART_INF_F); x1 = fmaxf(x1, q.y);
            m2 = fminf(m2, q.z > dv ? q.z : CUDART_INF_F); x2 = fmaxf(x2, q.z);
            m3 = fminf(m3, q.w > dv ? q.w : CUDART_INF_F); x3 = fmaxf(x3, q.w);
        }
        const float mg = fminf(fminf(m0, m1), fminf(m2, m3));  // min neg with d > dv
        const float mx = fmaxf(fmaxf(x0, x1), fmaxf(x2, x3));  // max over all negs
        const float v  = (mg < CUDART_INF_F) ? (dv - mg)       // semi-hard exists
                                             : (dv - mx);      // fallback: easiest neg
        contrib += fmaxf(v + 1.0f, 0.f);                       // relu(semi_hard+MARGIN)
    }
    if (contrib != 0.f) atomicAdd(&s_bsum, contrib);
    __syncthreads();   // barrier #2: s_bsum final

    // ---- last-block-done epilogue (single kernel) ----
    if (t == 0) {
        atomicAdd(&g_sum, s_bsum);
        atomicAdd(&g_cnt, (float)np);
        __threadfence();
        unsigned tk = atomicAdd(&g_ticket, 1u);
        if (tk == GRID - 1) {
            __threadfence();
            float s = atomicAdd(&g_sum, 0.f);
            float c = atomicAdd(&g_cnt, 0.f);
            out[0] = s / c;
            g_sum = 0.f;          // reset for next graph replay
            g_cnt = 0.f;
            __threadfence();
            g_ticket = 0u;
        }
    }
}

extern "C" void kernel_launch(void* const* d_in, const int* in_sizes, int n_in,
                              void* d_out, int out_size) {
    const float* emb    = (const float*)d_in[0];   // [256, 128] float32
    const int*   labraw = (const int*)d_in[1];     // [256] labels (int64/int32 detected)
    float* out = (float*)d_out;

    const int smem = 256 * ROWW * sizeof(float);   // 135168 B
    cudaFuncSetAttribute(triplet_fused, cudaFuncAttributeMaxDynamicSharedMemorySize, smem);
    triplet_fused<<<GRID, NT, smem>>>(emb, labraw, out);
}